// round 2
// baseline (speedup 1.0000x reference)
#include <cuda_runtime.h>
#include <cstddef>

// Mip chain: [6, 2048, 2048, 3] f32 -> 2x2 avg pool repeatedly down to 16.
// Output = concat(base, mip1..mip7), element offsets below.

#define R0 2048
#define OFF1 75497472ull    // 6*2048*2048*3
#define OFF2 94371840ull
#define OFF3 99090432ull
#define OFF4 100270080ull
#define OFF5 100564992ull
#define OFF6 100638720ull
#define OFF7 100657152ull

#define BLOCKS_PER_FACE 2048u   // grid 32 x 64 per face (64x32-px tiles)

__device__ unsigned int g_ctr[6];   // zero-init; self-resets each run

// One fused kernel:
//  - each block: 64x32 base tile of one face -> copy level0, produce mip1..mip5 for tile
//  - last block per face (atomic counter) -> mip5 -> mip6 -> mip7 for that face
__global__ __launch_bounds__(256) void mip_all(const float* __restrict__ base,
                                               float* __restrict__ out) {
    const int f  = blockIdx.z;
    const int tX = blockIdx.x;   // 0..31
    const int tY = blockIdx.y;   // 0..63
    const int t  = threadIdx.x;  // 0..255
    const int qy = t >> 4;       // 0..15
    const int qx = t & 15;       // 0..15

    __shared__ float sbuf[3072];   // s1..s4 for tile phase; s6 for last-block phase
    __shared__ int s_last;
    float* s1 = sbuf;             // 16*32*3 = 1536
    float* s2 = sbuf + 1536;      // 8*16*3  = 384
    float* s3 = sbuf + 1920;      // 4*8*3   = 96
    float* s4 = sbuf + 2016;      // 2*4*3   = 24

    // ---- stream: load 2 rows x 4 px (float4 x3 per row) ----
    const int y = tY * 32 + qy * 2;
    const int x = tX * 64 + qx * 4;
    const size_t r0off = ((size_t)(f * R0 + y) * R0 + x) * 3;
    const size_t r1off = r0off + (size_t)R0 * 3;

    const float4* pr0 = reinterpret_cast<const float4*>(base + r0off);
    const float4* pr1 = reinterpret_cast<const float4*>(base + r1off);
    float4 A0 = __ldcs(pr0), A1 = __ldcs(pr0 + 1), A2 = __ldcs(pr0 + 2);
    float4 B0 = __ldcs(pr1), B1 = __ldcs(pr1 + 1), B2 = __ldcs(pr1 + 2);

    // identity copy -> level 0
    float4* w0 = reinterpret_cast<float4*>(out + r0off);
    float4* w1 = reinterpret_cast<float4*>(out + r1off);
    __stcs(w0, A0); __stcs(w0 + 1, A1); __stcs(w0 + 2, A2);
    __stcs(w1, B0); __stcs(w1 + 1, B1); __stcs(w1 + 2, B2);

    // ---- mip1: 2 pixels per thread ----
    // row floats f0..f11 = 4 px RGB; A0=(f0..f3) A1=(f4..f7) A2=(f8..f11)
    float ar = (A0.x + A0.w + B0.x + B0.w) * 0.25f;
    float ag = (A0.y + A1.x + B0.y + B1.x) * 0.25f;
    float ab = (A0.z + A1.y + B0.z + B1.y) * 0.25f;
    float br = (A1.z + A2.y + B1.z + B2.y) * 0.25f;
    float bg = (A1.w + A2.z + B1.w + B2.z) * 0.25f;
    float bb = (A2.x + A2.w + B2.x + B2.w) * 0.25f;

    {
        const int y1 = tY * 16 + qy, x1 = tX * 32 + qx * 2;
        float* o = out + OFF1 + ((size_t)(f * 1024 + y1) * 1024 + x1) * 3;
        __stcs(reinterpret_cast<float2*>(o),     make_float2(ar, ag));
        __stcs(reinterpret_cast<float2*>(o) + 1, make_float2(ab, br));
        __stcs(reinterpret_cast<float2*>(o) + 2, make_float2(bg, bb));
        const int si = (qy * 32 + qx * 2) * 3;
        s1[si] = ar; s1[si + 1] = ag; s1[si + 2] = ab;
        s1[si + 3] = br; s1[si + 4] = bg; s1[si + 5] = bb;
    }
    __syncthreads();

    // ---- mip2: 16x8 (128 threads) ----
    if (t < 128) {
        const int ly = t >> 4, lx = t & 15;
        float vr = 0.f, vg = 0.f, vb = 0.f;
        #pragma unroll
        for (int dy = 0; dy < 2; dy++)
            #pragma unroll
            for (int dx = 0; dx < 2; dx++) {
                const int i = ((2 * ly + dy) * 32 + (2 * lx + dx)) * 3;
                vr += s1[i]; vg += s1[i + 1]; vb += s1[i + 2];
            }
        vr *= 0.25f; vg *= 0.25f; vb *= 0.25f;
        const size_t o = OFF2 + ((size_t)(f * 512 + tY * 8 + ly) * 512 + tX * 16 + lx) * 3;
        out[o] = vr; out[o + 1] = vg; out[o + 2] = vb;
        const int si = (ly * 16 + lx) * 3;
        s2[si] = vr; s2[si + 1] = vg; s2[si + 2] = vb;
    }
    __syncthreads();

    // ---- mip3: 8x4 (32 threads) ----
    if (t < 32) {
        const int ly = t >> 3, lx = t & 7;
        float vr = 0.f, vg = 0.f, vb = 0.f;
        #pragma unroll
        for (int dy = 0; dy < 2; dy++)
            #pragma unroll
            for (int dx = 0; dx < 2; dx++) {
                const int i = ((2 * ly + dy) * 16 + (2 * lx + dx)) * 3;
                vr += s2[i]; vg += s2[i + 1]; vb += s2[i + 2];
            }
        vr *= 0.25f; vg *= 0.25f; vb *= 0.25f;
        const size_t o = OFF3 + ((size_t)(f * 256 + tY * 4 + ly) * 256 + tX * 8 + lx) * 3;
        out[o] = vr; out[o + 1] = vg; out[o + 2] = vb;
        const int si = (ly * 8 + lx) * 3;
        s3[si] = vr; s3[si + 1] = vg; s3[si + 2] = vb;
    }
    __syncthreads();

    // ---- mip4: 4x2 (8 threads) ----
    if (t < 8) {
        const int ly = t >> 2, lx = t & 3;
        float vr = 0.f, vg = 0.f, vb = 0.f;
        #pragma unroll
        for (int dy = 0; dy < 2; dy++)
            #pragma unroll
            for (int dx = 0; dx < 2; dx++) {
                const int i = ((2 * ly + dy) * 8 + (2 * lx + dx)) * 3;
                vr += s3[i]; vg += s3[i + 1]; vb += s3[i + 2];
            }
        vr *= 0.25f; vg *= 0.25f; vb *= 0.25f;
        const size_t o = OFF4 + ((size_t)(f * 128 + tY * 2 + ly) * 128 + tX * 4 + lx) * 3;
        out[o] = vr; out[o + 1] = vg; out[o + 2] = vb;
        const int si = (ly * 4 + lx) * 3;
        s4[si] = vr; s4[si + 1] = vg; s4[si + 2] = vb;
    }
    __syncthreads();

    // ---- mip5: 2x1 per block ----
    if (t < 2) {
        #pragma unroll
        for (int c = 0; c < 3; c++) {
            float v = (s4[(0 * 4 + 2 * t) * 3 + c] + s4[(0 * 4 + 2 * t + 1) * 3 + c] +
                       s4[(1 * 4 + 2 * t) * 3 + c] + s4[(1 * 4 + 2 * t + 1) * 3 + c]) * 0.25f;
            out[OFF5 + ((size_t)(f * 64 + tY) * 64 + tX * 2 + t) * 3 + c] = v;
        }
    }

    // ---- per-face completion: last block does mip6 + mip7 ----
    __threadfence();
    __syncthreads();
    if (t == 0) {
        unsigned int old = atomicAdd(&g_ctr[f], 1u);
        if (old == BLOCKS_PER_FACE - 1u) {
            g_ctr[f] = 0u;          // self-reset for graph replay determinism
            s_last = 1;
        } else {
            s_last = 0;
        }
    }
    __syncthreads();
    if (!s_last) return;

    // last block of face f: mip5 (64x64) -> mip6 (32x32) -> mip7 (16x16)
    const float* m5 = out + OFF5 + (size_t)f * 64 * 64 * 3;
    float* m6 = out + OFF6 + (size_t)f * 32 * 32 * 3;
    float* m7 = out + OFF7 + (size_t)f * 16 * 16 * 3;
    float* s6 = sbuf;  // 32*32*3 = 3072 floats (tile smem no longer needed)

    #pragma unroll
    for (int p = t; p < 1024; p += 256) {
        const int yy = p >> 5, xx = p & 31;
        const float2* u0 = reinterpret_cast<const float2*>(m5 + ((2 * yy) * 64 + 2 * xx) * 3);
        const float2* u1 = reinterpret_cast<const float2*>(m5 + ((2 * yy + 1) * 64 + 2 * xx) * 3);
        float2 a0 = u0[0], a1 = u0[1], a2 = u0[2];
        float2 b0 = u1[0], b1 = u1[1], b2 = u1[2];
        float vr = (a0.x + a1.y + b0.x + b1.y) * 0.25f;
        float vg = (a0.y + a2.x + b0.y + b2.x) * 0.25f;
        float vb = (a1.x + a2.y + b1.x + b2.y) * 0.25f;
        m6[p * 3] = vr; m6[p * 3 + 1] = vg; m6[p * 3 + 2] = vb;
        s6[p * 3] = vr; s6[p * 3 + 1] = vg; s6[p * 3 + 2] = vb;
    }
    __syncthreads();
    {
        const int yy = t >> 4, xx = t & 15;
        #pragma unroll
        for (int c = 0; c < 3; c++) {
            float v = (s6[((2 * yy) * 32 + 2 * xx) * 3 + c] +
                       s6[((2 * yy) * 32 + 2 * xx + 1) * 3 + c] +
                       s6[((2 * yy + 1) * 32 + 2 * xx) * 3 + c] +
                       s6[((2 * yy + 1) * 32 + 2 * xx + 1) * 3 + c]) * 0.25f;
            m7[t * 3 + c] = v;
        }
    }
}

extern "C" void kernel_launch(void* const* d_in, const int* in_sizes, int n_in,
                              void* d_out, int out_size) {
    const float* base = (const float*)d_in[0];
    float* out = (float*)d_out;
    dim3 g(32, 64, 6);
    mip_all<<<g, 256>>>(base, out);
}

// round 3
// speedup vs baseline: 1.1494x; 1.1494x over previous
#include <cuda_runtime.h>
#include <cstddef>

// Mip chain: [6, 2048, 2048, 3] f32 -> 2x2 avg pool down to 16.
// Output = concat(base, mip1..mip7).

#define R0 2048
#define OFF1 75497472ull
#define OFF2 94371840ull
#define OFF3 99090432ull
#define OFF4 100270080ull
#define OFF5 100564992ull
#define OFF6 100638720ull
#define OFF7 100657152ull

// smem layout (floats)
#define S_SLAB 0        // 16 rows x 384 = 6144
#define S_M1   6144     // 8 rows x 192  = 1536
#define S_M2   7680     // 32 x 96       = 3072
#define S_M3   0        // reuse slab: 16 x 48 = 768
#define S_M4   1024     // 8 x 24 = 192
#define S_M5   2048     // 4 x 12 = 48
#define S_M6   2560     // 2 x 6  = 12
#define SMEM_FLOATS 10752

// One block = 128x128 base tile -> produces its piece of every level incl. its
// single mip7 pixel. No inter-block sync needed anywhere.
__global__ __launch_bounds__(256) void mip_all(const float* __restrict__ base,
                                               float* __restrict__ out) {
    __shared__ float sm[SMEM_FLOATS];
    const int f  = blockIdx.z;
    const int tX = blockIdx.x;   // 0..15
    const int tY = blockIdx.y;   // 0..15
    const int t  = threadIdx.x;  // 0..255

    // ---------- 8 slabs of 16 base rows ----------
    for (int s = 0; s < 8; s++) {
        const int y0 = tY * 128 + s * 16;

        // dense load: 1536 float4 (16 rows x 96 f4), lane-contiguous
        #pragma unroll
        for (int k = 0; k < 6; k++) {
            const int i   = k * 256 + t;
            const int row = i / 96;
            const int cf4 = i - row * 96;
            const size_t g = ((size_t)(f * R0 + y0 + row) * R0 + tX * 128) * 3;
            const float4 v = reinterpret_cast<const float4*>(base + g)[cf4];
            reinterpret_cast<float4*>(out + g)[cf4] = v;        // level-0 copy
            reinterpret_cast<float4*>(sm + S_SLAB)[row * 96 + cf4] = v;
        }
        __syncthreads();

        // mip1 slab: 8 rows x 64 px; 2 adjacent px per thread
        {
            const int idx = 2 * t;
            const int r1 = idx >> 6;        // 0..7
            const int c1 = idx & 63;        // even
            const float* ra = sm + S_SLAB + (2 * r1) * 384 + c1 * 6;
            const float* rb = ra + 384;
            float v[6];
            #pragma unroll
            for (int p = 0; p < 2; p++) {
                #pragma unroll
                for (int c = 0; c < 3; c++) {
                    v[p * 3 + c] = (ra[p * 6 + c] + ra[p * 6 + 3 + c] +
                                    rb[p * 6 + c] + rb[p * 6 + 3 + c]) * 0.25f;
                }
            }
            const int y1 = tY * 64 + s * 8 + r1;
            const int x1 = tX * 64 + c1;
            float2* o = reinterpret_cast<float2*>(out + OFF1 +
                         ((size_t)(f * 1024 + y1) * 1024 + x1) * 3);
            o[0] = make_float2(v[0], v[1]);
            o[1] = make_float2(v[2], v[3]);
            o[2] = make_float2(v[4], v[5]);
            float* m1 = sm + S_M1 + r1 * 192 + c1 * 3;
            #pragma unroll
            for (int j = 0; j < 6; j++) m1[j] = v[j];
        }
        __syncthreads();

        // mip2 slab: 4 rows x 32 px; threads 0..127
        if (t < 128) {
            const int r2 = t >> 5;          // 0..3
            const int c2 = t & 31;
            const float* ra = sm + S_M1 + (2 * r2) * 192 + c2 * 6;
            const float* rb = ra + 192;
            float vr = (ra[0] + ra[3] + rb[0] + rb[3]) * 0.25f;
            float vg = (ra[1] + ra[4] + rb[1] + rb[4]) * 0.25f;
            float vb = (ra[2] + ra[5] + rb[2] + rb[5]) * 0.25f;
            const int y2 = tY * 32 + s * 4 + r2;
            const int x2 = tX * 32 + c2;
            float* o = out + OFF2 + ((size_t)(f * 512 + y2) * 512 + x2) * 3;
            o[0] = vr; o[1] = vg; o[2] = vb;
            float* m2 = sm + S_M2 + (s * 4 + r2) * 96 + c2 * 3;
            m2[0] = vr; m2[1] = vg; m2[2] = vb;
        }
        __syncthreads();
    }

    // ---------- mip3: 16x16, one px per thread ----------
    {
        const int r = t >> 4, c = t & 15;
        const float* ra = sm + S_M2 + (2 * r) * 96 + c * 6;
        const float* rb = ra + 96;
        float vr = (ra[0] + ra[3] + rb[0] + rb[3]) * 0.25f;
        float vg = (ra[1] + ra[4] + rb[1] + rb[4]) * 0.25f;
        float vb = (ra[2] + ra[5] + rb[2] + rb[5]) * 0.25f;
        float* o = out + OFF3 + ((size_t)(f * 256 + tY * 16 + r) * 256 + tX * 16 + c) * 3;
        o[0] = vr; o[1] = vg; o[2] = vb;
        __syncthreads();                     // m2 reads done before reusing slab region
        float* m3 = sm + S_M3 + r * 48 + c * 3;
        m3[0] = vr; m3[1] = vg; m3[2] = vb;
    }
    __syncthreads();

    // ---------- mip4: 8x8 ----------
    if (t < 64) {
        const int r = t >> 3, c = t & 7;
        const float* ra = sm + S_M3 + (2 * r) * 48 + c * 6;
        const float* rb = ra + 48;
        float vr = (ra[0] + ra[3] + rb[0] + rb[3]) * 0.25f;
        float vg = (ra[1] + ra[4] + rb[1] + rb[4]) * 0.25f;
        float vb = (ra[2] + ra[5] + rb[2] + rb[5]) * 0.25f;
        float* o = out + OFF4 + ((size_t)(f * 128 + tY * 8 + r) * 128 + tX * 8 + c) * 3;
        o[0] = vr; o[1] = vg; o[2] = vb;
        float* m4 = sm + S_M4 + r * 24 + c * 3;
        m4[0] = vr; m4[1] = vg; m4[2] = vb;
    }
    __syncthreads();

    // ---------- mip5: 4x4 ----------
    if (t < 16) {
        const int r = t >> 2, c = t & 3;
        const float* ra = sm + S_M4 + (2 * r) * 24 + c * 6;
        const float* rb = ra + 24;
        float vr = (ra[0] + ra[3] + rb[0] + rb[3]) * 0.25f;
        float vg = (ra[1] + ra[4] + rb[1] + rb[4]) * 0.25f;
        float vb = (ra[2] + ra[5] + rb[2] + rb[5]) * 0.25f;
        float* o = out + OFF5 + ((size_t)(f * 64 + tY * 4 + r) * 64 + tX * 4 + c) * 3;
        o[0] = vr; o[1] = vg; o[2] = vb;
        float* m5 = sm + S_M5 + r * 12 + c * 3;
        m5[0] = vr; m5[1] = vg; m5[2] = vb;
    }
    __syncthreads();

    // ---------- mip6: 2x2 ----------
    if (t < 4) {
        const int r = t >> 1, c = t & 1;
        const float* ra = sm + S_M5 + (2 * r) * 12 + c * 6;
        const float* rb = ra + 12;
        float vr = (ra[0] + ra[3] + rb[0] + rb[3]) * 0.25f;
        float vg = (ra[1] + ra[4] + rb[1] + rb[4]) * 0.25f;
        float vb = (ra[2] + ra[5] + rb[2] + rb[5]) * 0.25f;
        float* o = out + OFF6 + ((size_t)(f * 32 + tY * 2 + r) * 32 + tX * 2 + c) * 3;
        o[0] = vr; o[1] = vg; o[2] = vb;
        float* m6 = sm + S_M6 + r * 6 + c * 3;
        m6[0] = vr; m6[1] = vg; m6[2] = vb;
    }
    __syncthreads();

    // ---------- mip7: 1 px per block ----------
    if (t == 0) {
        const float* m6 = sm + S_M6;
        float* o = out + OFF7 + ((size_t)(f * 16 + tY) * 16 + tX) * 3;
        #pragma unroll
        for (int c = 0; c < 3; c++)
            o[c] = (m6[c] + m6[3 + c] + m6[6 + c] + m6[9 + c]) * 0.25f;
    }
}

extern "C" void kernel_launch(void* const* d_in, const int* in_sizes, int n_in,
                              void* d_out, int out_size) {
    const float* base = (const float*)d_in[0];
    float* out = (float*)d_out;
    dim3 g(16, 16, 6);
    mip_all<<<g, 256>>>(base, out);
}

// round 4
// speedup vs baseline: 1.1976x; 1.0419x over previous
#include <cuda_runtime.h>
#include <cstddef>

// Mip chain: [6, 2048, 2048, 3] f32 -> repeated 2x2 avg pool down to 16.
// Output = concat(base, mip1..mip7).

#define R0 2048
#define OFF1 75497472ull
#define OFF2 94371840ull
#define OFF3 99090432ull
#define OFF4 100270080ull
#define OFF5 100564992ull
#define OFF6 100638720ull
#define OFF7 100657152ull

// smem layout (floats)
#define S_SLAB 0        // 8 sum-rows x 384 = 3072
#define S_M1   3072     // 8 x 192 = 1536
#define S_M2   4608     // 32 x 96 = 3072
#define S_M3   0        // reuse slab region
#define S_M4   1024
#define S_M5   2048
#define S_M6   2560
#define SMEM_FLOATS 7680

// One block = 128x128 base tile -> its piece of every level incl. one mip7 px.
// Vertical-pair dense loads + register prefetch of the next slab.
__global__ __launch_bounds__(256) void mip_all(const float* __restrict__ base,
                                               float* __restrict__ out) {
    __shared__ float sm[SMEM_FLOATS];
    const int f  = blockIdx.z;
    const int tX = blockIdx.x;   // 0..15
    const int tY = blockIdx.y;   // 0..15
    const int t  = threadIdx.x;  // 0..255

    // Each thread owns 3 (row-pair, f4-col) units per slab:
    // unit = k*256 + t; a = unit/96 (row pair 0..7), c = unit%96 (f4 col).
    int aa[3], cc[3];
    #pragma unroll
    for (int k = 0; k < 3; k++) {
        const int unit = k * 256 + t;
        aa[k] = unit / 96;
        cc[k] = unit - aa[k] * 96;
    }

    float4 va[3], vb[3];
    // preload slab 0
    #pragma unroll
    for (int k = 0; k < 3; k++) {
        const size_t g0 = ((size_t)(f * R0 + tY * 128 + 2 * aa[k]) * R0 + tX * 128) * 3;
        va[k] = reinterpret_cast<const float4*>(base + g0)[cc[k]];
        vb[k] = reinterpret_cast<const float4*>(base + g0 + (size_t)R0 * 3)[cc[k]];
    }

    for (int s = 0; s < 8; s++) {
        const int y0 = tY * 128 + s * 16;

        // ---- L0 copy + vertical sums into slab smem (dense stores) ----
        #pragma unroll
        for (int k = 0; k < 3; k++) {
            const size_t g0 = ((size_t)(f * R0 + y0 + 2 * aa[k]) * R0 + tX * 128) * 3;
            reinterpret_cast<float4*>(out + g0)[cc[k]] = va[k];
            reinterpret_cast<float4*>(out + g0 + (size_t)R0 * 3)[cc[k]] = vb[k];
            float4 sv;
            sv.x = va[k].x + vb[k].x;
            sv.y = va[k].y + vb[k].y;
            sv.z = va[k].z + vb[k].z;
            sv.w = va[k].w + vb[k].w;
            reinterpret_cast<float4*>(sm + S_SLAB)[aa[k] * 96 + cc[k]] = sv;
        }
        __syncthreads();

        // ---- prefetch next slab (in flight during mip1/mip2) ----
        if (s < 7) {
            #pragma unroll
            for (int k = 0; k < 3; k++) {
                const size_t g0 = ((size_t)(f * R0 + y0 + 16 + 2 * aa[k]) * R0 + tX * 128) * 3;
                va[k] = reinterpret_cast<const float4*>(base + g0)[cc[k]];
                vb[k] = reinterpret_cast<const float4*>(base + g0 + (size_t)R0 * 3)[cc[k]];
            }
        }

        // ---- mip1: 8 rows x 64 px; 2 adjacent px per thread ----
        {
            const int r1 = t >> 5;          // 0..7
            const int c1 = (t & 31) * 2;    // 0..62 even
            const float* in = sm + S_SLAB + r1 * 384 + c1 * 6;  // vertical sums
            const float v0 = (in[0] + in[3]) * 0.25f;
            const float v1 = (in[1] + in[4]) * 0.25f;
            const float v2 = (in[2] + in[5]) * 0.25f;
            const float v3 = (in[6] + in[9]) * 0.25f;
            const float v4 = (in[7] + in[10]) * 0.25f;
            const float v5 = (in[8] + in[11]) * 0.25f;
            const int y1 = tY * 64 + s * 8 + r1;
            const int x1 = tX * 64 + c1;
            float2* o = reinterpret_cast<float2*>(out + OFF1 +
                          ((size_t)(f * 1024 + y1) * 1024 + x1) * 3);
            o[0] = make_float2(v0, v1);
            o[1] = make_float2(v2, v3);
            o[2] = make_float2(v4, v5);
            float* m1 = sm + S_M1 + r1 * 192 + c1 * 3;
            m1[0] = v0; m1[1] = v1; m1[2] = v2;
            m1[3] = v3; m1[4] = v4; m1[5] = v5;
        }
        __syncthreads();

        // ---- mip2: 4 rows x 32 px (threads 0..127) ----
        if (t < 128) {
            const int r2 = t >> 5;          // 0..3
            const int c2 = t & 31;
            const float* ra = sm + S_M1 + (2 * r2) * 192 + c2 * 6;
            const float* rb = ra + 192;
            const float vr = (ra[0] + ra[3] + rb[0] + rb[3]) * 0.25f;
            const float vg = (ra[1] + ra[4] + rb[1] + rb[4]) * 0.25f;
            const float vb2 = (ra[2] + ra[5] + rb[2] + rb[5]) * 0.25f;
            const int y2 = tY * 32 + s * 4 + r2;
            const int x2 = tX * 32 + c2;
            float* o = out + OFF2 + ((size_t)(f * 512 + y2) * 512 + x2) * 3;
            o[0] = vr; o[1] = vg; o[2] = vb2;
            float* m2 = sm + S_M2 + (s * 4 + r2) * 96 + c2 * 3;
            m2[0] = vr; m2[1] = vg; m2[2] = vb2;
        }
        // no barrier here: next slab-write (S_SLAB) is disjoint from m1/m2.
    }
    __syncthreads();

    // ---- mip3: 16x16, 1 px per thread ----
    {
        const int r = t >> 4, c = t & 15;
        const float* ra = sm + S_M2 + (2 * r) * 96 + c * 6;
        const float* rb = ra + 96;
        const float vr = (ra[0] + ra[3] + rb[0] + rb[3]) * 0.25f;
        const float vg = (ra[1] + ra[4] + rb[1] + rb[4]) * 0.25f;
        const float vb2 = (ra[2] + ra[5] + rb[2] + rb[5]) * 0.25f;
        float* o = out + OFF3 + ((size_t)(f * 256 + tY * 16 + r) * 256 + tX * 16 + c) * 3;
        o[0] = vr; o[1] = vg; o[2] = vb2;
        float* m3 = sm + S_M3 + r * 48 + c * 3;
        m3[0] = vr; m3[1] = vg; m3[2] = vb2;
    }
    __syncthreads();

    // ---- mip4: 8x8 ----
    if (t < 64) {
        const int r = t >> 3, c = t & 7;
        const float* ra = sm + S_M3 + (2 * r) * 48 + c * 6;
        const float* rb = ra + 48;
        const float vr = (ra[0] + ra[3] + rb[0] + rb[3]) * 0.25f;
        const float vg = (ra[1] + ra[4] + rb[1] + rb[4]) * 0.25f;
        const float vb2 = (ra[2] + ra[5] + rb[2] + rb[5]) * 0.25f;
        float* o = out + OFF4 + ((size_t)(f * 128 + tY * 8 + r) * 128 + tX * 8 + c) * 3;
        o[0] = vr; o[1] = vg; o[2] = vb2;
        float* m4 = sm + S_M4 + r * 24 + c * 3;
        m4[0] = vr; m4[1] = vg; m4[2] = vb2;
    }
    __syncthreads();

    // ---- mip5: 4x4 ----
    if (t < 16) {
        const int r = t >> 2, c = t & 3;
        const float* ra = sm + S_M4 + (2 * r) * 24 + c * 6;
        const float* rb = ra + 24;
        const float vr = (ra[0] + ra[3] + rb[0] + rb[3]) * 0.25f;
        const float vg = (ra[1] + ra[4] + rb[1] + rb[4]) * 0.25f;
        const float vb2 = (ra[2] + ra[5] + rb[2] + rb[5]) * 0.25f;
        float* o = out + OFF5 + ((size_t)(f * 64 + tY * 4 + r) * 64 + tX * 4 + c) * 3;
        o[0] = vr; o[1] = vg; o[2] = vb2;
        float* m5 = sm + S_M5 + r * 12 + c * 3;
        m5[0] = vr; m5[1] = vg; m5[2] = vb2;
    }
    __syncthreads();

    // ---- mip6: 2x2 ----
    if (t < 4) {
        const int r = t >> 1, c = t & 1;
        const float* ra = sm + S_M5 + (2 * r) * 12 + c * 6;
        const float* rb = ra + 12;
        const float vr = (ra[0] + ra[3] + rb[0] + rb[3]) * 0.25f;
        const float vg = (ra[1] + ra[4] + rb[1] + rb[4]) * 0.25f;
        const float vb2 = (ra[2] + ra[5] + rb[2] + rb[5]) * 0.25f;
        float* o = out + OFF6 + ((size_t)(f * 32 + tY * 2 + r) * 32 + tX * 2 + c) * 3;
        o[0] = vr; o[1] = vg; o[2] = vb2;
        float* m6 = sm + S_M6 + r * 6 + c * 3;
        m6[0] = vr; m6[1] = vg; m6[2] = vb2;
    }
    __syncthreads();

    // ---- mip7: 1 px per block ----
    if (t == 0) {
        const float* m6 = sm + S_M6;
        float* o = out + OFF7 + ((size_t)(f * 16 + tY) * 16 + tX) * 3;
        #pragma unroll
        for (int c = 0; c < 3; c++)
            o[c] = (m6[c] + m6[3 + c] + m6[6 + c] + m6[9 + c]) * 0.25f;
    }
}

extern "C" void kernel_launch(void* const* d_in, const int* in_sizes, int n_in,
                              void* d_out, int out_size) {
    const float* base = (const float*)d_in[0];
    float* out = (float*)d_out;
    dim3 g(16, 16, 6);
    mip_all<<<g, 256>>>(base, out);
}

// round 5
// speedup vs baseline: 1.2065x; 1.0075x over previous
#include <cuda_runtime.h>
#include <cstddef>

// Mip chain: [6, 2048, 2048, 3] f32 -> repeated 2x2 avg pool down to 16.
// Output = concat(base, mip1..mip7).

#define R0 2048
#define OFF1 75497472ull
#define OFF2 94371840ull
#define OFF3 99090432ull
#define OFF4 100270080ull
#define OFF5 100564992ull
#define OFF6 100638720ull
#define OFF7 100657152ull

// smem layout (floats)
#define S_SLAB 0        // 8 sum-rows x 384 = 3072
#define S_M1   3072     // 8 x 192 = 1536
#define S_M2   4608     // 32 x 96 = 3072
#define S_M3   0        // reuse slab region
#define S_M4   1024
#define S_M5   2048
#define S_M6   2560
#define SMEM_FLOATS 7680

// One block = 128x128 base tile -> its piece of every level incl. one mip7 px.
// Vertical-pair dense loads + register prefetch of the next slab.
__global__ __launch_bounds__(256) void mip_all(const float* __restrict__ base,
                                               float* __restrict__ out) {
    __shared__ float sm[SMEM_FLOATS];
    const int f  = blockIdx.z;
    const int tX = blockIdx.x;   // 0..15
    const int tY = blockIdx.y;   // 0..15
    const int t  = threadIdx.x;  // 0..255

    // Each thread owns 3 (row-pair, f4-col) units per slab:
    // unit = k*256 + t; a = unit/96 (row pair 0..7), c = unit%96 (f4 col).
    int aa[3], cc[3];
    #pragma unroll
    for (int k = 0; k < 3; k++) {
        const int unit = k * 256 + t;
        aa[k] = unit / 96;
        cc[k] = unit - aa[k] * 96;
    }

    float4 va[3], vb[3];
    // preload slab 0
    #pragma unroll
    for (int k = 0; k < 3; k++) {
        const size_t g0 = ((size_t)(f * R0 + tY * 128 + 2 * aa[k]) * R0 + tX * 128) * 3;
        va[k] = reinterpret_cast<const float4*>(base + g0)[cc[k]];
        vb[k] = reinterpret_cast<const float4*>(base + g0 + (size_t)R0 * 3)[cc[k]];
    }

    for (int s = 0; s < 8; s++) {
        const int y0 = tY * 128 + s * 16;

        // ---- L0 copy + vertical sums into slab smem (dense stores) ----
        #pragma unroll
        for (int k = 0; k < 3; k++) {
            const size_t g0 = ((size_t)(f * R0 + y0 + 2 * aa[k]) * R0 + tX * 128) * 3;
            reinterpret_cast<float4*>(out + g0)[cc[k]] = va[k];
            reinterpret_cast<float4*>(out + g0 + (size_t)R0 * 3)[cc[k]] = vb[k];
            float4 sv;
            sv.x = va[k].x + vb[k].x;
            sv.y = va[k].y + vb[k].y;
            sv.z = va[k].z + vb[k].z;
            sv.w = va[k].w + vb[k].w;
            reinterpret_cast<float4*>(sm + S_SLAB)[aa[k] * 96 + cc[k]] = sv;
        }
        __syncthreads();

        // ---- prefetch next slab (in flight during mip1/mip2) ----
        if (s < 7) {
            #pragma unroll
            for (int k = 0; k < 3; k++) {
                const size_t g0 = ((size_t)(f * R0 + y0 + 16 + 2 * aa[k]) * R0 + tX * 128) * 3;
                va[k] = reinterpret_cast<const float4*>(base + g0)[cc[k]];
                vb[k] = reinterpret_cast<const float4*>(base + g0 + (size_t)R0 * 3)[cc[k]];
            }
        }

        // ---- mip1: 8 rows x 64 px; 2 adjacent px per thread ----
        {
            const int r1 = t >> 5;          // 0..7
            const int c1 = (t & 31) * 2;    // 0..62 even
            const float* in = sm + S_SLAB + r1 * 384 + c1 * 6;  // vertical sums
            const float v0 = (in[0] + in[3]) * 0.25f;
            const float v1 = (in[1] + in[4]) * 0.25f;
            const float v2 = (in[2] + in[5]) * 0.25f;
            const float v3 = (in[6] + in[9]) * 0.25f;
            const float v4 = (in[7] + in[10]) * 0.25f;
            const float v5 = (in[8] + in[11]) * 0.25f;
            const int y1 = tY * 64 + s * 8 + r1;
            const int x1 = tX * 64 + c1;
            float2* o = reinterpret_cast<float2*>(out + OFF1 +
                          ((size_t)(f * 1024 + y1) * 1024 + x1) * 3);
            o[0] = make_float2(v0, v1);
            o[1] = make_float2(v2, v3);
            o[2] = make_float2(v4, v5);
            float* m1 = sm + S_M1 + r1 * 192 + c1 * 3;
            m1[0] = v0; m1[1] = v1; m1[2] = v2;
            m1[3] = v3; m1[4] = v4; m1[5] = v5;
        }
        __syncthreads();

        // ---- mip2: 4 rows x 32 px (threads 0..127) ----
        if (t < 128) {
            const int r2 = t >> 5;          // 0..3
            const int c2 = t & 31;
            const float* ra = sm + S_M1 + (2 * r2) * 192 + c2 * 6;
            const float* rb = ra + 192;
            const float vr = (ra[0] + ra[3] + rb[0] + rb[3]) * 0.25f;
            const float vg = (ra[1] + ra[4] + rb[1] + rb[4]) * 0.25f;
            const float vb2 = (ra[2] + ra[5] + rb[2] + rb[5]) * 0.25f;
            const int y2 = tY * 32 + s * 4 + r2;
            const int x2 = tX * 32 + c2;
            float* o = out + OFF2 + ((size_t)(f * 512 + y2) * 512 + x2) * 3;
            o[0] = vr; o[1] = vg; o[2] = vb2;
            float* m2 = sm + S_M2 + (s * 4 + r2) * 96 + c2 * 3;
            m2[0] = vr; m2[1] = vg; m2[2] = vb2;
        }
        // no barrier here: next slab-write (S_SLAB) is disjoint from m1/m2.
    }
    __syncthreads();

    // ---- mip3: 16x16, 1 px per thread ----
    {
        const int r = t >> 4, c = t & 15;
        const float* ra = sm + S_M2 + (2 * r) * 96 + c * 6;
        const float* rb = ra + 96;
        const float vr = (ra[0] + ra[3] + rb[0] + rb[3]) * 0.25f;
        const float vg = (ra[1] + ra[4] + rb[1] + rb[4]) * 0.25f;
        const float vb2 = (ra[2] + ra[5] + rb[2] + rb[5]) * 0.25f;
        float* o = out + OFF3 + ((size_t)(f * 256 + tY * 16 + r) * 256 + tX * 16 + c) * 3;
        o[0] = vr; o[1] = vg; o[2] = vb2;
        float* m3 = sm + S_M3 + r * 48 + c * 3;
        m3[0] = vr; m3[1] = vg; m3[2] = vb2;
    }
    __syncthreads();

    // ---- mip4: 8x8 ----
    if (t < 64) {
        const int r = t >> 3, c = t & 7;
        const float* ra = sm + S_M3 + (2 * r) * 48 + c * 6;
        const float* rb = ra + 48;
        const float vr = (ra[0] + ra[3] + rb[0] + rb[3]) * 0.25f;
        const float vg = (ra[1] + ra[4] + rb[1] + rb[4]) * 0.25f;
        const float vb2 = (ra[2] + ra[5] + rb[2] + rb[5]) * 0.25f;
        float* o = out + OFF4 + ((size_t)(f * 128 + tY * 8 + r) * 128 + tX * 8 + c) * 3;
        o[0] = vr; o[1] = vg; o[2] = vb2;
        float* m4 = sm + S_M4 + r * 24 + c * 3;
        m4[0] = vr; m4[1] = vg; m4[2] = vb2;
    }
    __syncthreads();

    // ---- mip5: 4x4 ----
    if (t < 16) {
        const int r = t >> 2, c = t & 3;
        const float* ra = sm + S_M4 + (2 * r) * 24 + c * 6;
        const float* rb = ra + 24;
        const float vr = (ra[0] + ra[3] + rb[0] + rb[3]) * 0.25f;
        const float vg = (ra[1] + ra[4] + rb[1] + rb[4]) * 0.25f;
        const float vb2 = (ra[2] + ra[5] + rb[2] + rb[5]) * 0.25f;
        float* o = out + OFF5 + ((size_t)(f * 64 + tY * 4 + r) * 64 + tX * 4 + c) * 3;
        o[0] = vr; o[1] = vg; o[2] = vb2;
        float* m5 = sm + S_M5 + r * 12 + c * 3;
        m5[0] = vr; m5[1] = vg; m5[2] = vb2;
    }
    __syncthreads();

    // ---- mip6: 2x2 ----
    if (t < 4) {
        const int r = t >> 1, c = t & 1;
        const float* ra = sm + S_M5 + (2 * r) * 12 + c * 6;
        const float* rb = ra + 12;
        const float vr = (ra[0] + ra[3] + rb[0] + rb[3]) * 0.25f;
        const float vg = (ra[1] + ra[4] + rb[1] + rb[4]) * 0.25f;
        const float vb2 = (ra[2] + ra[5] + rb[2] + rb[5]) * 0.25f;
        float* o = out + OFF6 + ((size_t)(f * 32 + tY * 2 + r) * 32 + tX * 2 + c) * 3;
        o[0] = vr; o[1] = vg; o[2] = vb2;
        float* m6 = sm + S_M6 + r * 6 + c * 3;
        m6[0] = vr; m6[1] = vg; m6[2] = vb2;
    }
    __syncthreads();

    // ---- mip7: 1 px per block ----
    if (t == 0) {
        const float* m6 = sm + S_M6;
        float* o = out + OFF7 + ((size_t)(f * 16 + tY) * 16 + tX) * 3;
        #pragma unroll
        for (int c = 0; c < 3; c++)
            o[c] = (m6[c] + m6[3 + c] + m6[6 + c] + m6[9 + c]) * 0.25f;
    }
}

extern "C" void kernel_launch(void* const* d_in, const int* in_sizes, int n_in,
                              void* d_out, int out_size) {
    const float* base = (const float*)d_in[0];
    float* out = (float*)d_out;
    dim3 g(16, 16, 6);
    mip_all<<<g, 256>>>(base, out);
}